// round 3
// baseline (speedup 1.0000x reference)
#include <cuda_runtime.h>
#include <cuda_fp16.h>
#include <math.h>
#include <cstdint>

// Problem constants
#define BB 2
#define TT 2048
#define DD 1024
#define NH 16
#define HD 64
#define LOG2E_ 1.442695041f

// Scratch (allocation-free rule: __device__ globals)
__device__ float g_q[4194304];      // [B,T,N,H] = [4096,1024]
__device__ float g_k[4194304];
__device__ float g_v[4194304];
__device__ float g_attn[4194304];
__device__ float g_wt[3 * 1048576]; // wq/wk/wv transposed to [n][k]

// ---------------------------------------------------------------------------
// HMMA helpers (non-'a' ISA: works on plain sm_103 target)
// ---------------------------------------------------------------------------
__device__ __forceinline__ uint32_t smem_u32(const void* p) {
    uint32_t a;
    asm("{ .reg .u64 t; cvta.to.shared.u64 t, %1; cvt.u32.u64 %0, t; }" : "=r"(a) : "l"(p));
    return a;
}

__device__ __forceinline__ void ldsm_x4(uint32_t* r, uint32_t addr) {
    asm volatile("ldmatrix.sync.aligned.m8n8.x4.shared.b16 {%0,%1,%2,%3}, [%4];"
                 : "=r"(r[0]), "=r"(r[1]), "=r"(r[2]), "=r"(r[3]) : "r"(addr));
}

__device__ __forceinline__ void mma16816(float* c, const uint32_t* a, uint32_t b0, uint32_t b1) {
    asm volatile(
        "mma.sync.aligned.m16n8k16.row.col.f32.f16.f16.f32 "
        "{%0,%1,%2,%3}, {%4,%5,%6,%7}, {%8,%9}, {%0,%1,%2,%3};"
        : "+f"(c[0]), "+f"(c[1]), "+f"(c[2]), "+f"(c[3])
        : "r"(a[0]), "r"(a[1]), "r"(a[2]), "r"(a[3]), "r"(b0), "r"(b1));
}

// Swizzled byte offset for half tile with 64-half (128B) rows
__device__ __forceinline__ uint32_t swz_h(int r, int k) {
    return (uint32_t)(r * 128 + ((((k >> 3) ^ (r & 7))) << 4) + ((k & 7) << 1));
}

__device__ __forceinline__ uint32_t pack_h2(__half a, __half b) {
    __half2 h = __halves2half2(a, b);
    return *(uint32_t*)&h;
}

// Split a float4 into hi/lo fp16 pairs packed as 2x uint32 each
__device__ __forceinline__ void split4(float4 v, uint2& hi, uint2& lo) {
    __half hx = __float2half_rn(v.x), hy = __float2half_rn(v.y);
    __half hz = __float2half_rn(v.z), hw = __float2half_rn(v.w);
    hi.x = pack_h2(hx, hy);
    hi.y = pack_h2(hz, hw);
    lo.x = pack_h2(__float2half_rn(v.x - __half2float(hx)),
                   __float2half_rn(v.y - __half2float(hy)));
    lo.y = pack_h2(__float2half_rn(v.z - __half2float(hz)),
                   __float2half_rn(v.w - __half2float(hw)));
}

// SMEM: 4 tiles of [128 rows][64 halves] = 16KB each
#define TILE_B 16384
#define OFF_AHI 0
#define OFF_ALO (TILE_B)
#define OFF_BHI (2 * TILE_B)
#define OFF_BLO (3 * TILE_B)
#define GEMM_SMEM (4 * TILE_B)

// ---------------------------------------------------------------------------
// HMMA split-fp16 GEMM tile: C[row0:+128, col0:+128] = A @ Bt^T (+bias, +opt scale)
// A [4096][1024] row-major fp32, Bt [1024 n][1024 k] row-major fp32 (K-major).
// 256 threads = 8 warps; warp tile 32(m) x 64(n).
// ---------------------------------------------------------------------------
__device__ __forceinline__ void gemm_tile_hmma(
    const float* __restrict__ A, const float* __restrict__ Bt,
    const float* __restrict__ bias, const float* __restrict__ pds,
    float* __restrict__ C, int row0, int col0, char* smem)
{
    const int tid  = threadIdx.x;
    const int wid  = tid >> 5, lane = tid & 31;
    const int wm   = wid & 3, wn = wid >> 2;       // 4 x 2 warp grid
    const int m0   = wm * 32, n0 = wn * 64;
    const uint32_t sb = smem_u32(smem);

    float acc[2][8][4];
#pragma unroll
    for (int i = 0; i < 2; ++i)
#pragma unroll
        for (int j = 0; j < 8; ++j)
#pragma unroll
            for (int c = 0; c < 4; ++c) acc[i][j][c] = 0.f;

    // per-lane ldmatrix address components (row/col within 16-row x 16-col frags)
    const int lrow = lane & 15;
    const int lkof = (lane & 16) >> 1;   // 0 or 8

    for (int k0 = 0; k0 < 1024; k0 += 64) {
        // ---- load 128x64 fp32 of A and B, split hi/lo, swizzled store ----
#pragma unroll
        for (int it = 0; it < 8; ++it) {
            int idx = it * 256 + tid;          // 0..2047
            int r = idx >> 4, c4 = idx & 15;   // row, float4-col
            int k = c4 * 4;
            uint32_t off = swz_h(r, k);
            uint2 hi, lo;
            split4(*(const float4*)&A[(size_t)(row0 + r) * 1024 + k0 + k], hi, lo);
            *(uint2*)(smem + OFF_AHI + off) = hi;
            *(uint2*)(smem + OFF_ALO + off) = lo;
            split4(*(const float4*)&Bt[(size_t)(col0 + r) * 1024 + k0 + k], hi, lo);
            *(uint2*)(smem + OFF_BHI + off) = hi;
            *(uint2*)(smem + OFF_BLO + off) = lo;
        }
        __syncthreads();

        // ---- compute: 4 k16 steps ----
#pragma unroll
        for (int kk = 0; kk < 64; kk += 16) {
            uint32_t ah[2][4], al[2][4];
#pragma unroll
            for (int mi = 0; mi < 2; ++mi) {
                uint32_t o = swz_h(m0 + mi * 16 + lrow, kk + lkof);
                ldsm_x4(ah[mi], sb + OFF_AHI + o);
                ldsm_x4(al[mi], sb + OFF_ALO + o);
            }
            uint32_t bh[4][4], bl[4][4];
#pragma unroll
            for (int g = 0; g < 4; ++g) {
                uint32_t o = swz_h(n0 + g * 16 + lrow, kk + lkof);
                ldsm_x4(bh[g], sb + OFF_BHI + o);
                ldsm_x4(bl[g], sb + OFF_BLO + o);
            }
#pragma unroll
            for (int mi = 0; mi < 2; ++mi) {
#pragma unroll
                for (int g = 0; g < 4; ++g) {
                    // n-tile 2g: B frag = (reg0, reg2); n-tile 2g+1: (reg1, reg3)
                    mma16816(acc[mi][2 * g],     ah[mi], bh[g][0], bh[g][2]);
                    mma16816(acc[mi][2 * g],     ah[mi], bl[g][0], bl[g][2]);
                    mma16816(acc[mi][2 * g],     al[mi], bh[g][0], bh[g][2]);
                    mma16816(acc[mi][2 * g + 1], ah[mi], bh[g][1], bh[g][3]);
                    mma16816(acc[mi][2 * g + 1], ah[mi], bl[g][1], bl[g][3]);
                    mma16816(acc[mi][2 * g + 1], al[mi], bh[g][1], bh[g][3]);
                }
            }
        }
        __syncthreads();
    }

    // ---- epilogue: frag (mi,nj): c0,c1 @ (row, col), c2,c3 @ (row+8, col) ----
    const int frow = m0 + (lane >> 2);
    const int fcol = n0 + 2 * (lane & 3);
#pragma unroll
    for (int mi = 0; mi < 2; ++mi) {
#pragma unroll
        for (int nj = 0; nj < 8; ++nj) {
            int col = col0 + fcol + nj * 8;
            float s0 = 1.f, s1 = 1.f;
            if (pds) {
                float p0 = pds[col & 63], p1 = pds[(col + 1) & 63];
                s0 = (LOG2E_ * 0.125f) * ((p0 > 20.f) ? p0 : log1pf(__expf(p0)));
                s1 = (LOG2E_ * 0.125f) * ((p1 > 20.f) ? p1 : log1pf(__expf(p1)));
            }
            float b0 = bias[col], b1 = bias[col + 1];
            int r0 = row0 + frow + mi * 16;
            float2 o0 = make_float2((acc[mi][nj][0] + b0) * s0, (acc[mi][nj][1] + b1) * s1);
            float2 o1 = make_float2((acc[mi][nj][2] + b0) * s0, (acc[mi][nj][3] + b1) * s1);
            *(float2*)&C[(size_t)r0 * 1024 + col]       = o0;
            *(float2*)&C[(size_t)(r0 + 8) * 1024 + col] = o1;
        }
    }
}

// QKV: grid (8, 32, 3)
__global__ __launch_bounds__(256)
void qkv_hmma_kernel(const float* __restrict__ X,
                     const float* __restrict__ Bq, const float* __restrict__ Bk,
                     const float* __restrict__ Bv, const float* __restrict__ pds)
{
    extern __shared__ char smem[];
    const int z = blockIdx.z;
    const float* Bt   = g_wt + (size_t)z * 1048576;
    const float* bias = (z == 0) ? Bq : (z == 1) ? Bk : Bv;
    float* C          = (z == 0) ? g_q : (z == 1) ? g_k : g_v;
    gemm_tile_hmma(X, Bt, bias, (z == 0) ? pds : nullptr, C,
                   blockIdx.y * 128, blockIdx.x * 128, smem);
}

// Output projection: grid (8, 32); Wo is already [d][nh] K-major
__global__ __launch_bounds__(256)
void out_hmma_kernel(const float* __restrict__ Wo, const float* __restrict__ Bo,
                     float* __restrict__ Out)
{
    extern __shared__ char smem[];
    gemm_tile_hmma(g_attn, Wo, Bo, nullptr, Out,
                   blockIdx.y * 128, blockIdx.x * 128, smem);
}

// ---------------------------------------------------------------------------
// Weight transpose: g_wt[z][n][k] = w_z[k][n]
// ---------------------------------------------------------------------------
__global__ __launch_bounds__(256) void transpose_w_kernel(
    const float* __restrict__ wq, const float* __restrict__ wk, const float* __restrict__ wv)
{
    __shared__ float t[32][33];
    const int z = blockIdx.z;
    const float* src = (z == 0) ? wq : (z == 1) ? wk : wv;
    float* dst = g_wt + (size_t)z * 1048576;
    const int tx = threadIdx.x, ty = threadIdx.y;
    const int x0 = blockIdx.x * 32;  // k
    const int y0 = blockIdx.y * 32;  // n
#pragma unroll
    for (int i = 0; i < 4; ++i)
        t[ty + i * 8][tx] = src[(size_t)(x0 + ty + i * 8) * 1024 + y0 + tx];
    __syncthreads();
#pragma unroll
    for (int i = 0; i < 4; ++i)
        dst[(size_t)(y0 + ty + i * 8) * 1024 + x0 + tx] = t[tx][ty + i * 8];
}

// ---------------------------------------------------------------------------
// Flash attention (FFMA fp32, unchanged / known-correct)
// ---------------------------------------------------------------------------
__global__ __launch_bounds__(256) void attn_kernel(const int* __restrict__ mask)
{
    extern __shared__ float sm[];
    float* sQ = sm;                    // [h][r], stride 68
    float* sK = sQ + 64 * 68;          // [h][s], stride 68
    float* sV = sK + 64 * 68;          // [s][h], stride 64
    float* sP = sV + 64 * 64;          // [s][r], stride 68

    const int tid = threadIdx.x;
    const int tx = tid & 15, ty = tid >> 4;
    const int q0 = blockIdx.x * 64;
    const int n  = blockIdx.y;
    const int b  = blockIdx.z;

#pragma unroll
    for (int it = 0; it < 4; ++it) {
        int idx = tid + it * 256;
        int r = idx >> 4, h4 = (idx & 15) << 2;
        float4 qv = *(const float4*)&g_q[((b * TT + q0 + r) * NH + n) * HD + h4];
        sQ[(h4 + 0) * 68 + r] = qv.x; sQ[(h4 + 1) * 68 + r] = qv.y;
        sQ[(h4 + 2) * 68 + r] = qv.z; sQ[(h4 + 3) * 68 + r] = qv.w;
    }

    float m_i[4], l_i[4], acc[4][4];
#pragma unroll
    for (int i = 0; i < 4; ++i) {
        m_i[i] = -3.0e38f; l_i[i] = 0.f;
#pragma unroll
        for (int j = 0; j < 4; ++j) acc[i][j] = 0.f;
    }
    __syncthreads();

    for (int st = 0; st < TT / 64; ++st) {
        const int s0 = st * 64;
#pragma unroll
        for (int it = 0; it < 4; ++it) {
            int idx = tid + it * 256;
            int s = idx >> 4, h4 = (idx & 15) << 2;
            int g = ((b * TT + s0 + s) * NH + n) * HD + h4;
            float4 kv = *(const float4*)&g_k[g];
            sK[(h4 + 0) * 68 + s] = kv.x; sK[(h4 + 1) * 68 + s] = kv.y;
            sK[(h4 + 2) * 68 + s] = kv.z; sK[(h4 + 3) * 68 + s] = kv.w;
            float4 vv = *(const float4*)&g_v[g];
            *(float4*)&sV[s * 64 + h4] = vv;
        }
        __syncthreads();

        float Sa[4][4];
#pragma unroll
        for (int i = 0; i < 4; ++i)
#pragma unroll
            for (int j = 0; j < 4; ++j) Sa[i][j] = 0.f;
#pragma unroll
        for (int h = 0; h < 64; ++h) {
            float qf[4], kf[4];
            *(float4*)&qf[0] = *(const float4*)&sQ[h * 68 + ty * 4];
            *(float4*)&kf[0] = *(const float4*)&sK[h * 68 + tx * 4];
#pragma unroll
            for (int i = 0; i < 4; ++i)
#pragma unroll
                for (int j = 0; j < 4; ++j)
                    Sa[i][j] = fmaf(qf[i], kf[j], Sa[i][j]);
        }

#pragma unroll
        for (int i = 0; i < 4; ++i) {
            const int4 mv = *(const int4*)&mask[(b * TT + q0 + ty * 4 + i) * TT + s0 + tx * 4];
            Sa[i][0] = mv.x ? Sa[i][0] : -1.0e9f;
            Sa[i][1] = mv.y ? Sa[i][1] : -1.0e9f;
            Sa[i][2] = mv.z ? Sa[i][2] : -1.0e9f;
            Sa[i][3] = mv.w ? Sa[i][3] : -1.0e9f;
        }

#pragma unroll
        for (int i = 0; i < 4; ++i) {
            float rm = fmaxf(fmaxf(Sa[i][0], Sa[i][1]), fmaxf(Sa[i][2], Sa[i][3]));
#pragma unroll
            for (int msk = 8; msk; msk >>= 1)
                rm = fmaxf(rm, __shfl_xor_sync(0xffffffffu, rm, msk));
            float mn = fmaxf(m_i[i], rm);
            float f = __expf(m_i[i] - mn);
            m_i[i] = mn;
            float rs = 0.f;
#pragma unroll
            for (int j = 0; j < 4; ++j) {
                float p = __expf(Sa[i][j] - mn);
                Sa[i][j] = p;
                rs += p;
            }
#pragma unroll
            for (int msk = 8; msk; msk >>= 1)
                rs += __shfl_xor_sync(0xffffffffu, rs, msk);
            l_i[i] = l_i[i] * f + rs;
#pragma unroll
            for (int j = 0; j < 4; ++j) acc[i][j] *= f;
        }

#pragma unroll
        for (int i = 0; i < 4; ++i)
#pragma unroll
            for (int j = 0; j < 4; ++j)
                sP[(tx * 4 + j) * 68 + ty * 4 + i] = Sa[i][j];
        __syncthreads();

#pragma unroll
        for (int s = 0; s < 64; ++s) {
            float pf[4], vf[4];
            *(float4*)&pf[0] = *(const float4*)&sP[s * 68 + ty * 4];
            *(float4*)&vf[0] = *(const float4*)&sV[s * 64 + tx * 4];
#pragma unroll
            for (int i = 0; i < 4; ++i)
#pragma unroll
                for (int j = 0; j < 4; ++j)
                    acc[i][j] = fmaf(pf[i], vf[j], acc[i][j]);
        }
        __syncthreads();
    }

#pragma unroll
    for (int i = 0; i < 4; ++i) {
        float inv = 1.0f / l_i[i];
        float4 o = make_float4(acc[i][0] * inv, acc[i][1] * inv,
                               acc[i][2] * inv, acc[i][3] * inv);
        *(float4*)&g_attn[((b * TT + q0 + ty * 4 + i) * NH + n) * HD + tx * 4] = o;
    }
}

// ---------------------------------------------------------------------------
// Launch
// ---------------------------------------------------------------------------
extern "C" void kernel_launch(void* const* d_in, const int* in_sizes, int n_in,
                              void* d_out, int out_size)
{
    const float* x    = (const float*)d_in[0];
    const int*   mask = (const int*)  d_in[1];
    const float* wq   = (const float*)d_in[2];
    const float* bq   = (const float*)d_in[3];
    const float* wk   = (const float*)d_in[4];
    const float* bk   = (const float*)d_in[5];
    const float* wv   = (const float*)d_in[6];
    const float* bv   = (const float*)d_in[7];
    const float* wo   = (const float*)d_in[8];
    const float* bo   = (const float*)d_in[9];
    const float* pds  = (const float*)d_in[10];
    float* out = (float*)d_out;

    const int attn_smem = (64 * 68 * 3 + 64 * 64) * (int)sizeof(float);
    cudaFuncSetAttribute(attn_kernel, cudaFuncAttributeMaxDynamicSharedMemorySize, attn_smem);
    cudaFuncSetAttribute(qkv_hmma_kernel, cudaFuncAttributeMaxDynamicSharedMemorySize, GEMM_SMEM);
    cudaFuncSetAttribute(out_hmma_kernel, cudaFuncAttributeMaxDynamicSharedMemorySize, GEMM_SMEM);

    transpose_w_kernel<<<dim3(32, 32, 3), dim3(32, 8)>>>(wq, wk, wv);
    qkv_hmma_kernel<<<dim3(8, 32, 3), 256, GEMM_SMEM>>>(x, bq, bk, bv, pds);
    attn_kernel<<<dim3(32, 16, 2), 256, attn_smem>>>(mask);
    out_hmma_kernel<<<dim3(8, 32), 256, GEMM_SMEM>>>(wo, bo, out);
}

// round 5
// speedup vs baseline: 3.6085x; 3.6085x over previous
#include <cuda_runtime.h>
#include <cuda_fp16.h>
#include <math.h>
#include <cstdint>

#define BB 2
#define TT 2048
#define DD 1024
#define NH 16
#define HD 64
#define LOG2E_ 1.442695041f

// ---------------------------------------------------------------------------
// Scratch (__device__ globals, allocation-free rule)
// ---------------------------------------------------------------------------
__device__ __half g_xhi[4194304], g_xlo[4194304];        // X split       [4096][1024]
__device__ __half g_wthi[3145728], g_wtlo[3145728];      // wq/wk/wv^T    [3][1024 n][1024 k]
__device__ __half g_wohi[1048576], g_wolo[1048576];      // wo split      [1024 d][1024 k]
__device__ __half g_qhi[4194304], g_qlo[4194304];        // q (scaled)    [4096][1024]
__device__ __half g_khi[4194304], g_klo[4194304];        // k             [4096][1024]
__device__ __half g_v16[4194304];                        // v fp16        [4096][1024]
__device__ __half g_ahi[4194304], g_alo[4194304];        // attn out      [4096][1024]

// ---------------------------------------------------------------------------
// PTX helpers
// ---------------------------------------------------------------------------
__device__ __forceinline__ uint32_t smem_u32(const void* p) {
    uint32_t a;
    asm("{ .reg .u64 t; cvta.to.shared.u64 t, %1; cvt.u32.u64 %0, t; }" : "=r"(a) : "l"(p));
    return a;
}
__device__ __forceinline__ void ldsm_x4(uint32_t* r, uint32_t a) {
    asm volatile("ldmatrix.sync.aligned.m8n8.x4.shared.b16 {%0,%1,%2,%3}, [%4];"
                 : "=r"(r[0]), "=r"(r[1]), "=r"(r[2]), "=r"(r[3]) : "r"(a));
}
__device__ __forceinline__ void ldsm_x4_t(uint32_t* r, uint32_t a) {
    asm volatile("ldmatrix.sync.aligned.m8n8.x4.trans.shared.b16 {%0,%1,%2,%3}, [%4];"
                 : "=r"(r[0]), "=r"(r[1]), "=r"(r[2]), "=r"(r[3]) : "r"(a));
}
__device__ __forceinline__ void mma16816(float* c, const uint32_t* a, uint32_t b0, uint32_t b1) {
    asm volatile(
        "mma.sync.aligned.m16n8k16.row.col.f32.f16.f16.f32 "
        "{%0,%1,%2,%3}, {%4,%5,%6,%7}, {%8,%9}, {%0,%1,%2,%3};"
        : "+f"(c[0]), "+f"(c[1]), "+f"(c[2]), "+f"(c[3])
        : "r"(a[0]), "r"(a[1]), "r"(a[2]), "r"(a[3]), "r"(b0), "r"(b1));
}
#define CP_A16(dst, src) \
    asm volatile("cp.async.cg.shared.global [%0], [%1], 16;" :: "r"(dst), "l"(src))
#define CP_COMMIT() asm volatile("cp.async.commit_group;" ::: "memory")
#define CP_WAIT0()  asm volatile("cp.async.wait_group 0;" ::: "memory")
#define CP_WAIT1()  asm volatile("cp.async.wait_group 1;" ::: "memory")

// swizzled byte offset, 64-half (128B) rows
__device__ __forceinline__ uint32_t swz_h(int r, int k) {
    return (uint32_t)(r * 128 + (((k >> 3) ^ (r & 7)) << 4) + ((k & 7) << 1));
}
__device__ __forceinline__ uint32_t pack_h2(__half a, __half b) {
    __half2 h = __halves2half2(a, b);
    return *(uint32_t*)&h;
}
// split two floats into packed hi / packed lo
__device__ __forceinline__ void split2(float x, float y, uint32_t& hi, uint32_t& lo) {
    __half hx = __float2half_rn(x), hy = __float2half_rn(y);
    hi = pack_h2(hx, hy);
    lo = pack_h2(__float2half_rn(x - __half2float(hx)),
                 __float2half_rn(y - __half2float(hy)));
}

// ---------------------------------------------------------------------------
// Split kernels (fp32 -> fp16 hi/lo)
// ---------------------------------------------------------------------------
__global__ __launch_bounds__(256) void split_kernel(
    const float* __restrict__ src, __half* __restrict__ hi, __half* __restrict__ lo, int n4)
{
    int i = blockIdx.x * 256 + threadIdx.x;
    if (i >= n4) return;
    float4 v = *(const float4*)&src[i * 4];
    uint32_t h0, l0, h1, l1;
    split2(v.x, v.y, h0, l0);
    split2(v.z, v.w, h1, l1);
    *(uint32_t*)&hi[i * 4] = h0; *(uint32_t*)&hi[i * 4 + 2] = h1;
    *(uint32_t*)&lo[i * 4] = l0; *(uint32_t*)&lo[i * 4 + 2] = l1;
}

// transpose [k][n] -> [n][k] + split, for wq/wk/wv
__global__ __launch_bounds__(256) void transpose_split_kernel(
    const float* __restrict__ wq, const float* __restrict__ wk, const float* __restrict__ wv)
{
    __shared__ float t[32][33];
    const int z = blockIdx.z;
    const float* src = (z == 0) ? wq : (z == 1) ? wk : wv;
    __half* dhi = g_wthi + (size_t)z * 1048576;
    __half* dlo = g_wtlo + (size_t)z * 1048576;
    const int tx = threadIdx.x, ty = threadIdx.y;
    const int x0 = blockIdx.x * 32;  // k
    const int y0 = blockIdx.y * 32;  // n
#pragma unroll
    for (int i = 0; i < 4; ++i)
        t[ty + i * 8][tx] = src[(size_t)(x0 + ty + i * 8) * 1024 + y0 + tx];
    __syncthreads();
#pragma unroll
    for (int i = 0; i < 4; ++i) {
        float v = t[tx][ty + i * 8];
        __half h = __float2half_rn(v);
        dhi[(size_t)(y0 + ty + i * 8) * 1024 + x0 + tx] = h;
        dlo[(size_t)(y0 + ty + i * 8) * 1024 + x0 + tx] =
            __float2half_rn(v - __half2float(h));
    }
}

// ---------------------------------------------------------------------------
// Unified split-fp16 HMMA GEMM: C(4096x1024) = A(4096x1024) @ B^T + bias
// 3-term: Ah*Bh + Ah*Bl + Al*Bh as 48 K-chunks of 64.
// modes: 0=Q (scale+bias, split out), 1=K (bias, split out),
//        2=V (bias, fp16 out), 3=O (bias, fp32 out)
// 256 thr, 8 warps (4m x 2n), warp tile 32x64, 128x128 CTA tile.
// ---------------------------------------------------------------------------
#define G_STAGE 16384
__global__ __launch_bounds__(256, 2) void gemm_split_kernel(
    const float* __restrict__ bq, const float* __restrict__ bk,
    const float* __restrict__ bv, const float* __restrict__ bo,
    const float* __restrict__ pds, float* __restrict__ out, int mode_base)
{
    extern __shared__ char smem[];
    const int mode = mode_base + blockIdx.z;

    const __half* Ahi = (mode < 3) ? g_xhi : g_ahi;
    const __half* Alo = (mode < 3) ? g_xlo : g_alo;
    const __half* Bhi = (mode < 3) ? g_wthi + (size_t)mode * 1048576 : g_wohi;
    const __half* Blo = (mode < 3) ? g_wtlo + (size_t)mode * 1048576 : g_wolo;
    const float* bias = (mode == 0) ? bq : (mode == 1) ? bk : (mode == 2) ? bv : bo;

    const int tid = threadIdx.x;
    const int wid = tid >> 5, lane = tid & 31;
    const int m0 = (wid & 3) * 32, n0 = (wid >> 2) * 64;
    const int row0 = blockIdx.y * 128, col0 = blockIdx.x * 128;
    const uint32_t sbA = smem_u32(smem);
    const uint32_t sbB = sbA + 2 * G_STAGE;
    const int lrow = lane & 15;
    const int lkof = (lane & 16) >> 1;

    float acc[2][8][4];
#pragma unroll
    for (int i = 0; i < 2; ++i)
#pragma unroll
        for (int j = 0; j < 8; ++j)
#pragma unroll
            for (int c = 0; c < 4; ++c) acc[i][j][c] = 0.f;

    // chunk issue
    auto issue = [&](int c, int st) {
        int t = c >> 4, k0 = (c & 15) << 6;
        const __half* Ap = (t < 2) ? Ahi : Alo;
        const __half* Bp = (t == 1) ? Blo : Bhi;
#pragma unroll
        for (int it = 0; it < 4; ++it) {
            int idx = it * 256 + tid;
            int r = idx >> 3, k8 = (idx & 7) << 3;
            CP_A16(sbA + st * G_STAGE + swz_h(r, k8),
                   Ap + (size_t)(row0 + r) * 1024 + k0 + k8);
            CP_A16(sbB + st * G_STAGE + swz_h(r, k8),
                   Bp + (size_t)(col0 + r) * 1024 + k0 + k8);
        }
        CP_COMMIT();
    };

    issue(0, 0);
    for (int c = 0; c < 48; ++c) {
        if (c + 1 < 48) { issue(c + 1, (c + 1) & 1); CP_WAIT1(); }
        else           { CP_WAIT0(); }
        __syncthreads();
        const uint32_t aoff = sbA + (c & 1) * G_STAGE;
        const uint32_t boff = sbB + (c & 1) * G_STAGE;
#pragma unroll
        for (int kk = 0; kk < 64; kk += 16) {
            uint32_t af[2][4], bf[4][4];
#pragma unroll
            for (int mi = 0; mi < 2; ++mi)
                ldsm_x4(af[mi], aoff + swz_h(m0 + mi * 16 + lrow, kk + lkof));
#pragma unroll
            for (int g = 0; g < 4; ++g)
                ldsm_x4(bf[g], boff + swz_h(n0 + g * 16 + lrow, kk + lkof));
#pragma unroll
            for (int mi = 0; mi < 2; ++mi)
#pragma unroll
                for (int g = 0; g < 4; ++g) {
                    mma16816(acc[mi][2 * g],     af[mi], bf[g][0], bf[g][2]);
                    mma16816(acc[mi][2 * g + 1], af[mi], bf[g][1], bf[g][3]);
                }
        }
        __syncthreads();
    }

    // epilogue
    const int frow = m0 + (lane >> 2);
    const int fcol = n0 + 2 * (lane & 3);
#pragma unroll
    for (int mi = 0; mi < 2; ++mi) {
#pragma unroll
        for (int nj = 0; nj < 8; ++nj) {
            int col = col0 + fcol + nj * 8;
            int r0 = row0 + frow + mi * 16;
            float b0 = bias[col], b1 = bias[col + 1];
            float v0 = acc[mi][nj][0] + b0, v1 = acc[mi][nj][1] + b1;
            float v2 = acc[mi][nj][2] + b0, v3 = acc[mi][nj][3] + b1;
            if (mode == 0) {
                float p0 = pds[col & 63], p1 = pds[(col + 1) & 63];
                float s0 = (LOG2E_ * 0.125f) * ((p0 > 20.f) ? p0 : log1pf(__expf(p0)));
                float s1 = (LOG2E_ * 0.125f) * ((p1 > 20.f) ? p1 : log1pf(__expf(p1)));
                v0 *= s0; v1 *= s1; v2 *= s0; v3 *= s1;
            }
            if (mode <= 1) {
                __half* Chi = (mode == 0) ? g_qhi : g_khi;
                __half* Clo = (mode == 0) ? g_qlo : g_klo;
                uint32_t h, l;
                split2(v0, v1, h, l);
                *(uint32_t*)&Chi[(size_t)r0 * 1024 + col] = h;
                *(uint32_t*)&Clo[(size_t)r0 * 1024 + col] = l;
                split2(v2, v3, h, l);
                *(uint32_t*)&Chi[(size_t)(r0 + 8) * 1024 + col] = h;
                *(uint32_t*)&Clo[(size_t)(r0 + 8) * 1024 + col] = l;
            } else if (mode == 2) {
                *(uint32_t*)&g_v16[(size_t)r0 * 1024 + col] =
                    pack_h2(__float2half_rn(v0), __float2half_rn(v1));
                *(uint32_t*)&g_v16[(size_t)(r0 + 8) * 1024 + col] =
                    pack_h2(__float2half_rn(v2), __float2half_rn(v3));
            } else {
                *(float2*)&out[(size_t)r0 * 1024 + col] = make_float2(v0, v1);
                *(float2*)&out[(size_t)(r0 + 8) * 1024 + col] = make_float2(v2, v3);
            }
        }
    }
}

// ---------------------------------------------------------------------------
// Flash attention, HMMA. Block = (64 q rows, head n, batch b), 128 thr / 4 warps.
// Each warp owns 16 q rows. QK^T: 3-term split (K=192). PV: P split (2 terms),
// V fp16, P register-resident. Output written split fp16 for out-projection.
// smem: Qh,Ql [64][64] + 2 stages of (Kh,Kl,V [64][64]) = 16KB + 48KB.
// ---------------------------------------------------------------------------
#define A_QOFF 0
#define A_KVOFF 16384
#define A_KVSTAGE 24576
#define ATTN_SMEM (16384 + 2 * 24576)
__global__ __launch_bounds__(128) void attn_hmma_kernel(const int* __restrict__ mask)
{
    extern __shared__ char smem[];
    const int tid = threadIdx.x;
    const int wid = tid >> 5, lane = tid & 31;
    const int q0 = blockIdx.x * 64;
    const int n  = blockIdx.y;
    const int b  = blockIdx.z;
    const uint32_t sb = smem_u32(smem);
    const int lrow = lane & 15;
    const int lkof = (lane & 16) >> 1;

    const size_t gq0 = (size_t)(b * TT + q0) * 1024 + n * 64;

    // prologue: Q (hi+lo) and KV tile 0 in one cp.async group
#pragma unroll
    for (int it = 0; it < 4; ++it) {
        int idx = it * 128 + tid;           // 0..511
        int r = idx >> 3, k8 = (idx & 7) << 3;
        CP_A16(sb + A_QOFF + swz_h(r, k8),        g_qhi + gq0 + (size_t)r * 1024 + k8);
        CP_A16(sb + A_QOFF + 8192 + swz_h(r, k8), g_qlo + gq0 + (size_t)r * 1024 + k8);
    }
    auto issue_kv = [&](int st, int stage) {
        size_t gk0 = (size_t)(b * TT + st * 64) * 1024 + n * 64;
        uint32_t base = sb + A_KVOFF + stage * A_KVSTAGE;
#pragma unroll
        for (int it = 0; it < 4; ++it) {
            int idx = it * 128 + tid;
            int r = idx >> 3, k8 = (idx & 7) << 3;
            size_t g = gk0 + (size_t)r * 1024 + k8;
            uint32_t o = swz_h(r, k8);
            CP_A16(base + o,         g_khi + g);
            CP_A16(base + 8192 + o,  g_klo + g);
            CP_A16(base + 16384 + o, g_v16 + g);
        }
        CP_COMMIT();
    };
    issue_kv(0, 0);   // commits group containing Q + KV0

    uint32_t qh[4][4], ql[4][4];
    float oacc[8][4];
#pragma unroll
    for (int j = 0; j < 8; ++j)
#pragma unroll
        for (int c = 0; c < 4; ++c) oacc[j][c] = 0.f;
    float m_0 = -3.0e38f, m_1 = -3.0e38f, l_0 = 0.f, l_1 = 0.f;

    const int qrl = q0 + wid * 16 + (lane >> 2);     // local q row (lo half)
    const int mcol0 = 2 * (lane & 3);

    for (int st = 0; st < TT / 64; ++st) {
        if (st + 1 < TT / 64) { issue_kv(st + 1, (st + 1) & 1); CP_WAIT1(); }
        else                  { CP_WAIT0(); }
        __syncthreads();

        if (st == 0) {
            // load Q fragments once
#pragma unroll
            for (int kt = 0; kt < 4; ++kt) {
                uint32_t o = swz_h(wid * 16 + lrow, kt * 16 + lkof);
                ldsm_x4(qh[kt], sb + A_QOFF + o);
                ldsm_x4(ql[kt], sb + A_QOFF + 8192 + o);
            }
        }

        const uint32_t kvb = sb + A_KVOFF + (st & 1) * A_KVSTAGE;

        // ---- S = QK^T (3 terms, 12 k16 steps) ----
        float sacc[8][4];
#pragma unroll
        for (int j = 0; j < 8; ++j)
#pragma unroll
            for (int c = 0; c < 4; ++c) sacc[j][c] = 0.f;
#pragma unroll
        for (int kt = 0; kt < 12; ++kt) {
            const int t = kt >> 2, kq = kt & 3;
            const uint32_t* af = (t < 2) ? qh[kq] : ql[kq];
            const uint32_t kb = (t == 1) ? kvb + 8192 : kvb;
            uint32_t bf[4][4];
#pragma unroll
            for (int g = 0; g < 4; ++g)
                ldsm_x4(bf[g], kb + swz_h(g * 16 + lrow, kq * 16 + lkof));
#pragma unroll
            for (int g = 0; g < 4; ++g) {
                mma16816(sacc[2 * g],     af, bf[g][0], bf[g][2]);
                mma16816(sacc[2 * g + 1], af, bf[g][1], bf[g][3]);
            }
        }

        // ---- mask ----
#pragma unroll
        for (int j = 0; j < 8; ++j) {
            int col = st * 64 + j * 8 + mcol0;
            int2 mv0 = *(const int2*)&mask[(size_t)(b * TT + qrl) * TT + col];
            int2 mv1 = *(const int2*)&mask[(size_t)(b * TT + qrl + 8) * TT + col];
            if (!mv0.x) sacc[j][0] = -1.0e9f;
            if (!mv0.y) sacc[j][1] = -1.0e9f;
            if (!mv1.x) sacc[j][2] = -1.0e9f;
            if (!mv1.y) sacc[j][3] = -1.0e9f;
        }

        // ---- online softmax ----
        float mx0 = -3.0e38f, mx1 = -3.0e38f;
#pragma unroll
        for (int j = 0; j < 8; ++j) {
            mx0 = fmaxf(mx0, fmaxf(sacc[j][0], sacc[j][1]));
            mx1 = fmaxf(mx1, fmaxf(sacc[j][2], sacc[j][3]));
        }
        mx0 = fmaxf(mx0, __shfl_xor_sync(0xffffffffu, mx0, 1));
        mx0 = fmaxf(mx0, __shfl_xor_sync(0xffffffffu, mx0, 2));
        mx1 = fmaxf(mx1, __shfl_xor_sync(0xffffffffu, mx1, 1));
        mx1 = fmaxf(mx1, __shfl_xor_sync(0xffffffffu, mx1, 2));
        float mn0 = fmaxf(m_0, mx0), mn1 = fmaxf(m_1, mx1);
        float f0 = __expf(m_0 - mn0), f1 = __expf(m_1 - mn1);
        m_0 = mn0; m_1 = mn1;
        float rs0 = 0.f, rs1 = 0.f;
#pragma unroll
        for (int j = 0; j < 8; ++j) {
            sacc[j][0] = __expf(sacc[j][0] - mn0);
            sacc[j][1] = __expf(sacc[j][1] - mn0);
            sacc[j][2] = __expf(sacc[j][2] - mn1);
            sacc[j][3] = __expf(sacc[j][3] - mn1);
            rs0 += sacc[j][0] + sacc[j][1];
            rs1 += sacc[j][2] + sacc[j][3];
        }
        rs0 += __shfl_xor_sync(0xffffffffu, rs0, 1);
        rs0 += __shfl_xor_sync(0xffffffffu, rs0, 2);
        rs1 += __shfl_xor_sync(0xffffffffu, rs1, 1);
        rs1 += __shfl_xor_sync(0xffffffffu, rs1, 2);
        l_0 = l_0 * f0 + rs0;
        l_1 = l_1 * f1 + rs1;
#pragma unroll
        for (int j = 0; j < 8; ++j) {
            oacc[j][0] *= f0; oacc[j][1] *= f0;
            oacc[j][2] *= f1; oacc[j][3] *= f1;
        }

        // ---- O += P V  (P split in registers, V fp16) ----
#pragma unroll
        for (int kt = 0; kt < 4; ++kt) {
            uint32_t ph[4], pl[4];
            {
                const float* sA = sacc[2 * kt];
                const float* sB = sacc[2 * kt + 1];
                __half h0 = __float2half_rn(sA[0]), h1 = __float2half_rn(sA[1]);
                ph[0] = pack_h2(h0, h1);
                pl[0] = pack_h2(__float2half_rn(sA[0] - __half2float(h0)),
                                __float2half_rn(sA[1] - __half2float(h1)));
                h0 = __float2half_rn(sA[2]); h1 = __float2half_rn(sA[3]);
                ph[1] = pack_h2(h0, h1);
                pl[1] = pack_h2(__float2half_rn(sA[2] - __half2float(h0)),
                                __float2half_rn(sA[3] - __half2float(h1)));
                h0 = __float2half_rn(sB[0]); h1 = __float2half_rn(sB[1]);
                ph[2] = pack_h2(h0, h1);
                pl[2] = pack_h2(__float2half_rn(sB[0] - __half2float(h0)),
                                __float2half_rn(sB[1] - __half2float(h1)));
                h0 = __float2half_rn(sB[2]); h1 = __float2half_rn(sB[3]);
                ph[3] = pack_h2(h0, h1);
                pl[3] = pack_h2(__float2half_rn(sB[2] - __half2float(h0)),
                                __float2half_rn(sB[3] - __half2float(h1)));
            }
            uint32_t vf[4][4];
#pragma unroll
            for (int g = 0; g < 4; ++g)
                ldsm_x4_t(vf[g], kvb + 16384 + swz_h(kt * 16 + lrow, g * 16 + lkof));
#pragma unroll
            for (int g = 0; g < 4; ++g) {
                mma16816(oacc[2 * g],     ph, vf[g][0], vf[g][1]);
                mma16816(oacc[2 * g],     pl, vf[g][0], vf[g][1]);
                mma16816(oacc[2 * g + 1], ph, vf[g][2], vf[g][3]);
                mma16816(oacc[2 * g + 1], pl, vf[g][2], vf[g][3]);
            }
        }
        __syncthreads();
    }

    // ---- epilogue: normalize + split fp16 store ----
    const float inv0 = 1.0f / l_0, inv1 = 1.0f / l_1;
    const size_t m_lo = (size_t)(b * TT + qrl) * 1024 + n * 64;
#pragma unroll
    for (int j = 0; j < 8; ++j) {
        int col = j * 8 + mcol0;
        uint32_t h, l;
        split2(oacc[j][0] * inv0, oacc[j][1] * inv0, h, l);
        *(uint32_t*)&g_ahi[m_lo + col] = h;
        *(uint32_t*)&g_alo[m_lo + col] = l;
        split2(oacc[j][2] * inv1, oacc[j][3] * inv1, h, l);
        *(uint32_t*)&g_ahi[m_lo + 8 * 1024 + col] = h;
        *(uint32_t*)&g_alo[m_lo + 8 * 1024 + col] = l;
    }
}

// ---------------------------------------------------------------------------
// Launch
// ---------------------------------------------------------------------------
extern "C" void kernel_launch(void* const* d_in, const int* in_sizes, int n_in,
                              void* d_out, int out_size)
{
    const float* x    = (const float*)d_in[0];
    const int*   mask = (const int*)  d_in[1];
    const float* wq   = (const float*)d_in[2];
    const float* bq   = (const float*)d_in[3];
    const float* wk   = (const float*)d_in[4];
    const float* bk   = (const float*)d_in[5];
    const float* wv   = (const float*)d_in[6];
    const float* bv   = (const float*)d_in[7];
    const float* wo   = (const float*)d_in[8];
    const float* bo   = (const float*)d_in[9];
    const float* pds  = (const float*)d_in[10];
    float* out = (float*)d_out;

    const int gemm_smem = 4 * G_STAGE;  // 64KB
    cudaFuncSetAttribute(gemm_split_kernel, cudaFuncAttributeMaxDynamicSharedMemorySize, gemm_smem);
    cudaFuncSetAttribute(attn_hmma_kernel, cudaFuncAttributeMaxDynamicSharedMemorySize, ATTN_SMEM);

    __half *xhi, *xlo, *wohi, *wolo;
    cudaGetSymbolAddress((void**)&xhi, g_xhi);
    cudaGetSymbolAddress((void**)&xlo, g_xlo);
    cudaGetSymbolAddress((void**)&wohi, g_wohi);
    cudaGetSymbolAddress((void**)&wolo, g_wolo);

    split_kernel<<<4096, 256>>>(x, xhi, xlo, 1048576);
    split_kernel<<<1024, 256>>>(wo, wohi, wolo, 262144);
    transpose_split_kernel<<<dim3(32, 32, 3), dim3(32, 8)>>>(wq, wk, wv);

    gemm_split_kernel<<<dim3(8, 32, 3), 256, gemm_smem>>>(bq, bk, bv, bo, pds, out, 0);
    attn_hmma_kernel<<<dim3(32, 16, 2), 128, ATTN_SMEM>>>(mask);
    gemm_split_kernel<<<dim3(8, 32, 1), 256, gemm_smem>>>(bq, bk, bv, bo, pds, out, 3);
}